// round 2
// baseline (speedup 1.0000x reference)
#include <cuda_runtime.h>

#define BATCH 4
#define NQ    2048
#define NK    2048
#define DQ    1024
#define NH    8
#define HD    64
#define INNER 512
#define KKEEP 64

// Scratch (device globals; allocation-free contract)
__device__ float g_Q [BATCH * NQ * INNER];          // 16.8 MB
__device__ float g_KV[BATCH * NK * 2 * INNER];      // 33.5 MB  (K: cols 0..511, V: 512..1023)
__device__ float g_S [134217728];                   // 512 MB   sim [B*H][NQ][NK]
__device__ float g_O [BATCH * NQ * INNER];          // 16.8 MB

// ---------------------------------------------------------------------------
// Generic fp32 SGEMM (NN): C[M,N] = A[M,K] @ B[K,N] (+ bias broadcast on N)
// 128x128 tile, BK=8, 256 threads, 8x8 per-thread microtile.
// Requires M%128==0, N%128==0, K%8==0 (true for all three uses).
// ---------------------------------------------------------------------------
__global__ void __launch_bounds__(256) sgemm_nn(
    const float* __restrict__ A, const float* __restrict__ Bm,
    const float* __restrict__ bias, float* __restrict__ C,
    int M, int N, int K)
{
    __shared__ float As[8][128];
    __shared__ float Bs[8][128];
    const int tid  = threadIdx.x;
    const int row0 = blockIdx.y * 128, col0 = blockIdx.x * 128;
    const int tx   = tid & 15, ty = tid >> 4;
    const int a_row = tid >> 1, a_k = (tid & 1) * 4;
    const int b_k   = tid >> 5, b_col = (tid & 31) * 4;
    const float* Ap = A  + (size_t)(row0 + a_row) * K + a_k;
    const float* Bp = Bm + (size_t)b_k * N + col0 + b_col;

    float acc[8][8];
#pragma unroll
    for (int i = 0; i < 8; i++)
#pragma unroll
        for (int j = 0; j < 8; j++) acc[i][j] = 0.f;

    for (int k0 = 0; k0 < K; k0 += 8) {
        float4 av = *(const float4*)(Ap + k0);
        float4 bv = *(const float4*)(Bp + (size_t)k0 * N);
        As[a_k + 0][a_row] = av.x;
        As[a_k + 1][a_row] = av.y;
        As[a_k + 2][a_row] = av.z;
        As[a_k + 3][a_row] = av.w;
        *(float4*)&Bs[b_k][b_col] = bv;
        __syncthreads();
#pragma unroll
        for (int kk = 0; kk < 8; kk++) {
            float af[8], bf[8];
            *(float4*)&af[0] = *(const float4*)&As[kk][ty * 4];
            *(float4*)&af[4] = *(const float4*)&As[kk][ty * 4 + 64];
            *(float4*)&bf[0] = *(const float4*)&Bs[kk][tx * 4];
            *(float4*)&bf[4] = *(const float4*)&Bs[kk][tx * 4 + 64];
#pragma unroll
            for (int i = 0; i < 8; i++)
#pragma unroll
                for (int j = 0; j < 8; j++)
                    acc[i][j] += af[i] * bf[j];
        }
        __syncthreads();
    }

#pragma unroll
    for (int ih = 0; ih < 2; ih++)
#pragma unroll
        for (int ii = 0; ii < 4; ii++) {
            int row = row0 + ty * 4 + ih * 64 + ii;
            float* Cp = C + (size_t)row * N + col0;
#pragma unroll
            for (int jh = 0; jh < 2; jh++) {
                int c = tx * 4 + jh * 64;
                float4 v;
                v.x = acc[ih * 4 + ii][jh * 4 + 0];
                v.y = acc[ih * 4 + ii][jh * 4 + 1];
                v.z = acc[ih * 4 + ii][jh * 4 + 2];
                v.w = acc[ih * 4 + ii][jh * 4 + 3];
                if (bias) {
                    v.x += bias[col0 + c + 0];
                    v.y += bias[col0 + c + 1];
                    v.z += bias[col0 + c + 2];
                    v.w += bias[col0 + c + 3];
                }
                *(float4*)(Cp + c) = v;
            }
        }
}

// ---------------------------------------------------------------------------
// sim[bh][i][j] = scale * sum_d Q[b,i,h*64+d] * K[b,j,h*64+d]   (NT GEMM, K=64)
// 64x64 tile, entire reduction dim in smem, 256 threads, 4x4 microtile.
// ---------------------------------------------------------------------------
__global__ void __launch_bounds__(256) sim_nt(
    const float* __restrict__ Q, const float* __restrict__ KV, float* __restrict__ S)
{
    __shared__ float Ast[64][68];   // [d][i], padded
    __shared__ float Bst[64][68];   // [d][j]
    const int bh = blockIdx.z, b = bh >> 3, h = bh & 7;
    const int i0 = blockIdx.y * 64, j0 = blockIdx.x * 64;
    const int tid = threadIdx.x;

#pragma unroll
    for (int l = 0; l < 4; l++) {
        int idx = tid + l * 256;
        int row = idx >> 4, d0 = (idx & 15) * 4;
        float4 a = *(const float4*)(Q  + (size_t)(b * NQ + i0 + row) * INNER     + h * HD + d0);
        Ast[d0 + 0][row] = a.x; Ast[d0 + 1][row] = a.y;
        Ast[d0 + 2][row] = a.z; Ast[d0 + 3][row] = a.w;
        float4 v = *(const float4*)(KV + (size_t)(b * NK + j0 + row) * (2 * INNER) + h * HD + d0);
        Bst[d0 + 0][row] = v.x; Bst[d0 + 1][row] = v.y;
        Bst[d0 + 2][row] = v.z; Bst[d0 + 3][row] = v.w;
    }
    __syncthreads();

    const int tx = tid & 15, ty = tid >> 4;
    float acc[4][4];
#pragma unroll
    for (int i = 0; i < 4; i++)
#pragma unroll
        for (int j = 0; j < 4; j++) acc[i][j] = 0.f;

#pragma unroll 8
    for (int d = 0; d < 64; d++) {
        float4 a  = *(const float4*)&Ast[d][ty * 4];
        float4 bb = *(const float4*)&Bst[d][tx * 4];
        float af[4] = {a.x, a.y, a.z, a.w};
        float bf[4] = {bb.x, bb.y, bb.z, bb.w};
#pragma unroll
        for (int i = 0; i < 4; i++)
#pragma unroll
            for (int j = 0; j < 4; j++)
                acc[i][j] += af[i] * bf[j];
    }

    const float scale = 0.125f;   // 64^-0.5
#pragma unroll
    for (int ii = 0; ii < 4; ii++) {
        float4 v;
        v.x = acc[ii][0] * scale; v.y = acc[ii][1] * scale;
        v.z = acc[ii][2] * scale; v.w = acc[ii][3] * scale;
        *(float4*)(S + ((size_t)bh * NQ + i0 + ty * 4 + ii) * NK + j0 + tx * 4) = v;
    }
}

// ---------------------------------------------------------------------------
// Per query row: exact top-64 (radix threshold via 2048-bin histogram on
// monotone float keys, ties broken by lowest index = jax.lax.top_k), softmax
// over survivors (masked entries underflow to exactly 0 in ref), sparse PV.
// One block (128 threads) per row.
// ---------------------------------------------------------------------------
__global__ void __launch_bounds__(128) topk_attn(
    const float* __restrict__ S, const float* __restrict__ KV, float* __restrict__ O)
{
    const int r  = blockIdx.x;
    const int bh = r >> 11, i = r & 2047;
    const int b  = bh >> 3, h = bh & 7;
    const float* srow = S + (size_t)r * NK;

    __shared__ unsigned hist[2048];
    __shared__ unsigned segsum[128];
    __shared__ float cval[2048];
    __shared__ int   cidx[2048];
    __shared__ float selv[80];
    __shared__ int   seli[80];
    __shared__ int   s_nsel, s_ncand, s_thrbin, s_m;
    __shared__ float s_max, s_wsum;
    __shared__ float w[64];
    __shared__ float part[64];

    const int tid = threadIdx.x;
    for (int t = tid; t < 2048; t += 128) hist[t] = 0u;
    if (tid == 0) { s_nsel = 0; s_ncand = 0; }
    __syncthreads();

    float vals[16];
#pragma unroll
    for (int t = 0; t < 4; t++) {
        float4 v = ((const float4*)srow)[tid + t * 128];
        vals[t * 4 + 0] = v.x; vals[t * 4 + 1] = v.y;
        vals[t * 4 + 2] = v.z; vals[t * 4 + 3] = v.w;
    }
#pragma unroll
    for (int t = 0; t < 16; t++) {
        unsigned u = __float_as_uint(vals[t]);
        unsigned key = (u & 0x80000000u) ? ~u : (u | 0x80000000u);
        atomicAdd(&hist[key >> 21], 1u);
    }
    __syncthreads();

    { unsigned s = 0;
      for (int q = 0; q < 16; q++) s += hist[tid * 16 + q];
      segsum[tid] = s; }
    __syncthreads();

    if (tid == 0) {
        unsigned c = 0; int sseg = 127;
        while (c + segsum[sseg] < KKEEP) { c += segsum[sseg]; sseg--; }
        int bin = sseg * 16 + 15;
        while (c + hist[bin] < KKEEP) { c += hist[bin]; bin--; }
        s_thrbin = bin;
        s_m = KKEEP - (int)c;
    }
    __syncthreads();
    const int thrbin = s_thrbin, m = s_m;

#pragma unroll
    for (int t = 0; t < 16; t++) {
        unsigned u = __float_as_uint(vals[t]);
        unsigned key = (u & 0x80000000u) ? ~u : (u | 0x80000000u);
        int bin = (int)(key >> 21);
        int j = (tid + (t >> 2) * 128) * 4 + (t & 3);
        if (bin > thrbin) {
            int p = atomicAdd(&s_nsel, 1);
            selv[p] = vals[t]; seli[p] = j;
        } else if (bin == thrbin) {
            int p = atomicAdd(&s_ncand, 1);
            cval[p] = vals[t]; cidx[p] = j;
        }
    }
    __syncthreads();

    const int ncand = s_ncand;
    for (int cpos = tid; cpos < ncand; cpos += 128) {
        float v = cval[cpos]; int jj = cidx[cpos];
        int rank = 0;
        for (int o = 0; o < ncand; o++) {
            float v2 = cval[o]; int j2 = cidx[o];
            rank += (v2 > v) || (v2 == v && j2 < jj);
        }
        if (rank < m) {
            int p = atomicAdd(&s_nsel, 1);
            selv[p] = v; seli[p] = jj;
        }
    }
    __syncthreads();   // s_nsel == 64 exactly

    if (tid < 32) {
        float mx = fmaxf(selv[tid], selv[tid + 32]);
#pragma unroll
        for (int off = 16; off; off >>= 1)
            mx = fmaxf(mx, __shfl_xor_sync(0xffffffffu, mx, off));
        if (tid == 0) s_max = mx;
    }
    __syncthreads();
    if (tid < 64) w[tid] = expf(selv[tid] - s_max);
    __syncthreads();
    if (tid < 32) {
        float s = w[tid] + w[tid + 32];
#pragma unroll
        for (int off = 16; off; off >>= 1)
            s += __shfl_xor_sync(0xffffffffu, s, off);
        if (tid == 0) s_wsum = s;
    }
    __syncthreads();

    const int g = tid >> 6, d = tid & 63;
    const float* Vbase = KV + (size_t)b * NK * (2 * INNER) + INNER + h * HD + d;
    float acc = 0.f;
#pragma unroll 4
    for (int jj = 0; jj < 32; jj++) {
        int j = g * 32 + jj;
        acc += w[j] * Vbase[(size_t)seli[j] * (2 * INNER)];
    }
    if (g == 1) part[d] = acc;
    __syncthreads();
    if (g == 0) {
        float o = (acc + part[d]) / s_wsum;
        O[((size_t)(b * NQ + i)) * INNER + h * HD + d] = o;
    }
}

// ---------------------------------------------------------------------------
extern "C" void kernel_launch(void* const* d_in, const int* in_sizes, int n_in,
                              void* d_out, int out_size)
{
    const float* x    = (const float*)d_in[0];
    const float* ctx  = (const float*)d_in[1];
    const float* Wq   = (const float*)d_in[2];
    const float* Wkv  = (const float*)d_in[3];
    const float* Wout = (const float*)d_in[4];
    const float* bout = (const float*)d_in[5];
    float* out = (float*)d_out;

    float *pQ, *pKV, *pS, *pO;
    cudaGetSymbolAddress((void**)&pQ,  g_Q);
    cudaGetSymbolAddress((void**)&pKV, g_KV);
    cudaGetSymbolAddress((void**)&pS,  g_S);
    cudaGetSymbolAddress((void**)&pO,  g_O);

    dim3 blk(256);
    // Q = x @ Wq            [8192,1024] @ [1024,512]
    sgemm_nn<<<dim3(INNER / 128, BATCH * NQ / 128), blk>>>(x, Wq, nullptr, pQ,
                                                           BATCH * NQ, INNER, DQ);
    // KV = ctx @ Wkv        [8192,1024] @ [1024,1024]
    sgemm_nn<<<dim3(2 * INNER / 128, BATCH * NK / 128), blk>>>(ctx, Wkv, nullptr, pKV,
                                                               BATCH * NK, 2 * INNER, DQ);
    // sim = Q @ K^T * scale (batched per head)
    sim_nt<<<dim3(NK / 64, NQ / 64, BATCH * NH), blk>>>(pQ, pKV, pS);
    // exact top-64 + softmax + sparse PV
    topk_attn<<<dim3(BATCH * NH * NQ), dim3(128)>>>(pS, pKV, pO);
    // out = O @ Wout + bout [8192,512] @ [512,1024]
    sgemm_nn<<<dim3(DQ / 128, BATCH * NQ / 128), blk>>>(pO, Wout, bout, out,
                                                        BATCH * NQ, DQ, INNER);
}

// round 3
// speedup vs baseline: 1.0048x; 1.0048x over previous
#include <cuda_runtime.h>

#define BATCH 4
#define NQ    2048
#define NK    2048
#define DQ    1024
#define NH    8
#define HD    64
#define INNER 512
#define KKEEP 64

// Scratch (device globals; allocation-free contract)
__device__ float g_Q [BATCH * NQ * INNER];          // 16.8 MB
__device__ float g_KV[BATCH * NK * 2 * INNER];      // 33.5 MB  (K: cols 0..511, V: 512..1023)
__device__ float g_S [134217728];                   // 512 MB   sim [B*H][NQ][NK]
__device__ float g_O [BATCH * NQ * INNER];          // 16.8 MB

// ---------------------------------------------------------------------------
// fp32 SGEMM (NN), double-buffered: C[M,N] = A[M,K] @ B[K,N] (+ bias)
// 128x128 tile, BK=8, 256 threads, 8x8 microtile, 2-stage smem pipeline.
// ---------------------------------------------------------------------------
__global__ void __launch_bounds__(256) sgemm_nn(
    const float* __restrict__ A, const float* __restrict__ Bm,
    const float* __restrict__ bias, float* __restrict__ C,
    int M, int N, int K)
{
    __shared__ float As[2][8][128];
    __shared__ float Bs[2][8][128];
    const int tid  = threadIdx.x;
    const int row0 = blockIdx.y * 128, col0 = blockIdx.x * 128;
    const int tx   = tid & 15, ty = tid >> 4;
    const int a_row = tid >> 1, a_k = (tid & 1) * 4;
    const int b_k   = tid >> 5, b_col = (tid & 31) * 4;
    const float* Ap = A  + (size_t)(row0 + a_row) * K + a_k;
    const float* Bp = Bm + (size_t)b_k * N + col0 + b_col;

    float acc[8][8];
#pragma unroll
    for (int i = 0; i < 8; i++)
#pragma unroll
        for (int j = 0; j < 8; j++) acc[i][j] = 0.f;

    // prologue: load first tile
    {
        float4 av = *(const float4*)Ap;
        float4 bv = *(const float4*)Bp;
        As[0][a_k + 0][a_row] = av.x;
        As[0][a_k + 1][a_row] = av.y;
        As[0][a_k + 2][a_row] = av.z;
        As[0][a_k + 3][a_row] = av.w;
        *(float4*)&Bs[0][b_k][b_col] = bv;
    }
    __syncthreads();

    int buf = 0;
    for (int k0 = 8; k0 <= K; k0 += 8) {
        const bool has = (k0 < K);
        float4 av, bv;
        if (has) {
            av = *(const float4*)(Ap + k0);
            bv = *(const float4*)(Bp + (size_t)k0 * N);
        }
#pragma unroll
        for (int kk = 0; kk < 8; kk++) {
            float af[8], bf[8];
            *(float4*)&af[0] = *(const float4*)&As[buf][kk][ty * 4];
            *(float4*)&af[4] = *(const float4*)&As[buf][kk][ty * 4 + 64];
            *(float4*)&bf[0] = *(const float4*)&Bs[buf][kk][tx * 4];
            *(float4*)&bf[4] = *(const float4*)&Bs[buf][kk][tx * 4 + 64];
#pragma unroll
            for (int i = 0; i < 8; i++)
#pragma unroll
                for (int j = 0; j < 8; j++)
                    acc[i][j] += af[i] * bf[j];
        }
        if (has) {
            const int nb = buf ^ 1;
            As[nb][a_k + 0][a_row] = av.x;
            As[nb][a_k + 1][a_row] = av.y;
            As[nb][a_k + 2][a_row] = av.z;
            As[nb][a_k + 3][a_row] = av.w;
            *(float4*)&Bs[nb][b_k][b_col] = bv;
            __syncthreads();
            buf = nb;
        }
    }

#pragma unroll
    for (int ih = 0; ih < 2; ih++)
#pragma unroll
        for (int ii = 0; ii < 4; ii++) {
            int row = row0 + ty * 4 + ih * 64 + ii;
            float* Cp = C + (size_t)row * N + col0;
#pragma unroll
            for (int jh = 0; jh < 2; jh++) {
                int c = tx * 4 + jh * 64;
                float4 v;
                v.x = acc[ih * 4 + ii][jh * 4 + 0];
                v.y = acc[ih * 4 + ii][jh * 4 + 1];
                v.z = acc[ih * 4 + ii][jh * 4 + 2];
                v.w = acc[ih * 4 + ii][jh * 4 + 3];
                if (bias) {
                    v.x += bias[col0 + c + 0];
                    v.y += bias[col0 + c + 1];
                    v.z += bias[col0 + c + 2];
                    v.w += bias[col0 + c + 3];
                }
                *(float4*)(Cp + c) = v;
            }
        }
}

// ---------------------------------------------------------------------------
// sim[bh][i][j] = scale * sum_d Q[b,i,h*64+d] * K[b,j,h*64+d]   (NT, K=64)
// 128x128 tile, whole K=64 in smem (64KB dynamic), 256 threads, 8x8 microtile.
// ---------------------------------------------------------------------------
__global__ void __launch_bounds__(256) sim_nt(
    const float* __restrict__ Q, const float* __restrict__ KV, float* __restrict__ S)
{
    extern __shared__ float smem[];
    float* Qs = smem;              // [64][128]  (d-major)
    float* Ks = smem + 64 * 128;   // [64][128]
    const int bh = blockIdx.z, b = bh >> 3, h = bh & 7;
    const int i0 = blockIdx.y * 128, j0 = blockIdx.x * 128;
    const int tid = threadIdx.x;

#pragma unroll
    for (int l = 0; l < 8; l++) {
        int idx = tid + l * 256;
        int row = idx >> 4, d0 = (idx & 15) * 4;
        float4 a = *(const float4*)(Q  + (size_t)(b * NQ + i0 + row) * INNER       + h * HD + d0);
        Qs[(d0 + 0) * 128 + row] = a.x; Qs[(d0 + 1) * 128 + row] = a.y;
        Qs[(d0 + 2) * 128 + row] = a.z; Qs[(d0 + 3) * 128 + row] = a.w;
        float4 v = *(const float4*)(KV + (size_t)(b * NK + j0 + row) * (2 * INNER) + h * HD + d0);
        Ks[(d0 + 0) * 128 + row] = v.x; Ks[(d0 + 1) * 128 + row] = v.y;
        Ks[(d0 + 2) * 128 + row] = v.z; Ks[(d0 + 3) * 128 + row] = v.w;
    }
    __syncthreads();

    const int tx = tid & 15, ty = tid >> 4;
    float acc[8][8];
#pragma unroll
    for (int i = 0; i < 8; i++)
#pragma unroll
        for (int j = 0; j < 8; j++) acc[i][j] = 0.f;

#pragma unroll 4
    for (int d = 0; d < 64; d++) {
        float af[8], bf[8];
        *(float4*)&af[0] = *(const float4*)(Qs + d * 128 + ty * 4);
        *(float4*)&af[4] = *(const float4*)(Qs + d * 128 + ty * 4 + 64);
        *(float4*)&bf[0] = *(const float4*)(Ks + d * 128 + tx * 4);
        *(float4*)&bf[4] = *(const float4*)(Ks + d * 128 + tx * 4 + 64);
#pragma unroll
        for (int i = 0; i < 8; i++)
#pragma unroll
            for (int j = 0; j < 8; j++)
                acc[i][j] += af[i] * bf[j];
    }

    const float scale = 0.125f;   // 64^-0.5
#pragma unroll
    for (int ih = 0; ih < 2; ih++)
#pragma unroll
        for (int ii = 0; ii < 4; ii++) {
            int row = i0 + ty * 4 + ih * 64 + ii;
            float* Sp = S + ((size_t)bh * NQ + row) * NK + j0;
#pragma unroll
            for (int jh = 0; jh < 2; jh++) {
                int c = tx * 4 + jh * 64;
                float4 v;
                v.x = acc[ih * 4 + ii][jh * 4 + 0] * scale;
                v.y = acc[ih * 4 + ii][jh * 4 + 1] * scale;
                v.z = acc[ih * 4 + ii][jh * 4 + 2] * scale;
                v.w = acc[ih * 4 + ii][jh * 4 + 3] * scale;
                *(float4*)(Sp + c) = v;
            }
        }
}

// ---------------------------------------------------------------------------
// Per query row: exact top-64 via two-level radix threshold (11-bit bins,
// then 8-bit mantissa refinement), ties broken by lowest index (= jax.lax.top_k),
// softmax over survivors, sparse PV. One block (128 threads) per row.
// ---------------------------------------------------------------------------
__device__ __forceinline__ unsigned fkey(float f) {
    unsigned u = __float_as_uint(f);
    return (u & 0x80000000u) ? ~u : (u | 0x80000000u);
}

__global__ void __launch_bounds__(128) topk_attn(
    const float* __restrict__ S, const float* __restrict__ KV, float* __restrict__ O)
{
    const int r  = blockIdx.x;
    const int bh = r >> 11, i = r & 2047;
    const int b  = bh >> 3, h = bh & 7;
    const float* srow = S + (size_t)r * NK;

    __shared__ unsigned hist[2048];
    __shared__ unsigned hist2[256];
    __shared__ unsigned segsum[128];
    __shared__ float cval[2048];
    __shared__ unsigned short cidx[2048];
    __shared__ float selv[80];
    __shared__ int   seli[80];
    __shared__ int   s_nsel, s_ncand, s_thrbin, s_m, s_sb, s_m2;
    __shared__ float s_max, s_wsum;
    __shared__ float w[64];
    __shared__ float part[64];

    const int tid = threadIdx.x;
    for (int t = tid; t < 2048; t += 128) hist[t] = 0u;
    if (tid == 0) { s_nsel = 0; s_ncand = 0; }
    __syncthreads();

    float vals[16];
#pragma unroll
    for (int t = 0; t < 4; t++) {
        float4 v = ((const float4*)srow)[tid + t * 128];
        vals[t * 4 + 0] = v.x; vals[t * 4 + 1] = v.y;
        vals[t * 4 + 2] = v.z; vals[t * 4 + 3] = v.w;
    }
#pragma unroll
    for (int t = 0; t < 16; t++)
        atomicAdd(&hist[fkey(vals[t]) >> 21], 1u);
    __syncthreads();

    { unsigned s = 0;
      for (int q = 0; q < 16; q++) s += hist[tid * 16 + q];
      segsum[tid] = s; }
    __syncthreads();

    if (tid == 0) {
        unsigned c = 0; int sseg = 127;
        while (c + segsum[sseg] < KKEEP) { c += segsum[sseg]; sseg--; }
        int bin = sseg * 16 + 15;
        while (c + hist[bin] < KKEEP) { c += hist[bin]; bin--; }
        s_thrbin = bin;
        s_m = KKEEP - (int)c;
    }
    __syncthreads();
    const int thrbin = s_thrbin, m = s_m;

#pragma unroll
    for (int t = 0; t < 16; t++) {
        int bin = (int)(fkey(vals[t]) >> 21);
        int j = (tid + (t >> 2) * 128) * 4 + (t & 3);
        if (bin > thrbin) {
            int p = atomicAdd(&s_nsel, 1);
            selv[p] = vals[t]; seli[p] = j;
        } else if (bin == thrbin) {
            int p = atomicAdd(&s_ncand, 1);
            cval[p] = vals[t]; cidx[p] = (unsigned short)j;
        }
    }
    __syncthreads();

    const int ncand = s_ncand;
    if (m == ncand) {
        // entire threshold bin survives
        for (int c = tid; c < ncand; c += 128) {
            int p = atomicAdd(&s_nsel, 1);
            selv[p] = cval[c]; seli[p] = cidx[c];
        }
    } else {
        // second-level refinement on mantissa bits [13:21)
        for (int t = tid; t < 256; t += 128) hist2[t] = 0u;
        __syncthreads();
        for (int c = tid; c < ncand; c += 128)
            atomicAdd(&hist2[(fkey(cval[c]) >> 13) & 0xFF], 1u);
        __syncthreads();
        if (tid == 0) {
            unsigned c2 = 0; int sb = 255;
            while (c2 + hist2[sb] < (unsigned)m) { c2 += hist2[sb]; sb--; }
            s_sb = sb; s_m2 = m - (int)c2;
        }
        __syncthreads();
        const int sb = s_sb, m2 = s_m2;
        for (int c = tid; c < ncand; c += 128) {
            int sbin = (int)((fkey(cval[c]) >> 13) & 0xFF);
            if (sbin > sb) {
                int p = atomicAdd(&s_nsel, 1);
                selv[p] = cval[c]; seli[p] = cidx[c];
            } else if (sbin == sb) {
                float v = cval[c]; int jj = cidx[c];
                int rank = 0;
                for (int o = 0; o < ncand; o++) {
                    if ((int)((fkey(cval[o]) >> 13) & 0xFF) != sb) continue;
                    float v2 = cval[o];
                    rank += (v2 > v) || (v2 == v && (int)cidx[o] < jj);
                }
                if (rank < m2) {
                    int p = atomicAdd(&s_nsel, 1);
                    selv[p] = v; seli[p] = jj;
                }
            }
        }
    }
    __syncthreads();   // s_nsel == 64 exactly

    if (tid < 32) {
        float mx = fmaxf(selv[tid], selv[tid + 32]);
#pragma unroll
        for (int off = 16; off; off >>= 1)
            mx = fmaxf(mx, __shfl_xor_sync(0xffffffffu, mx, off));
        if (tid == 0) s_max = mx;
    }
    __syncthreads();
    if (tid < 64) w[tid] = expf(selv[tid] - s_max);
    __syncthreads();
    if (tid < 32) {
        float s = w[tid] + w[tid + 32];
#pragma unroll
        for (int off = 16; off; off >>= 1)
            s += __shfl_xor_sync(0xffffffffu, s, off);
        if (tid == 0) s_wsum = s;
    }
    __syncthreads();

    const int g = tid >> 6, d = tid & 63;
    const float* Vbase = KV + (size_t)b * NK * (2 * INNER) + INNER + h * HD + d;
    float acc = 0.f;
#pragma unroll 4
    for (int jj = 0; jj < 32; jj++) {
        int j = g * 32 + jj;
        acc += w[j] * Vbase[(size_t)seli[j] * (2 * INNER)];
    }
    if (g == 1) part[d] = acc;
    __syncthreads();
    if (g == 0) {
        float o = (acc + part[d]) / s_wsum;
        O[((size_t)(b * NQ + i)) * INNER + h * HD + d] = o;
    }
}

// ---------------------------------------------------------------------------
extern "C" void kernel_launch(void* const* d_in, const int* in_sizes, int n_in,
                              void* d_out, int out_size)
{
    const float* x    = (const float*)d_in[0];
    const float* ctx  = (const float*)d_in[1];
    const float* Wq   = (const float*)d_in[2];
    const float* Wkv  = (const float*)d_in[3];
    const float* Wout = (const float*)d_in[4];
    const float* bout = (const float*)d_in[5];
    float* out = (float*)d_out;

    float *pQ, *pKV, *pS, *pO;
    cudaGetSymbolAddress((void**)&pQ,  g_Q);
    cudaGetSymbolAddress((void**)&pKV, g_KV);
    cudaGetSymbolAddress((void**)&pS,  g_S);
    cudaGetSymbolAddress((void**)&pO,  g_O);

    const int simSmem = 2 * 64 * 128 * sizeof(float);   // 64 KB
    cudaFuncSetAttribute(sim_nt, cudaFuncAttributeMaxDynamicSharedMemorySize, simSmem);

    dim3 blk(256);
    // Q = x @ Wq            [8192,1024] @ [1024,512]
    sgemm_nn<<<dim3(INNER / 128, BATCH * NQ / 128), blk>>>(x, Wq, nullptr, pQ,
                                                           BATCH * NQ, INNER, DQ);
    // KV = ctx @ Wkv        [8192,1024] @ [1024,1024]
    sgemm_nn<<<dim3(2 * INNER / 128, BATCH * NK / 128), blk>>>(ctx, Wkv, nullptr, pKV,
                                                               BATCH * NK, 2 * INNER, DQ);
    // sim = Q @ K^T * scale (batched per head)
    sim_nt<<<dim3(NK / 128, NQ / 128, BATCH * NH), blk, simSmem>>>(pQ, pKV, pS);
    // exact top-64 + softmax + sparse PV
    topk_attn<<<dim3(BATCH * NH * NQ), dim3(128)>>>(pS, pKV, pO);
    // out = O @ Wout + bout [8192,512] @ [512,1024]
    sgemm_nn<<<dim3(DQ / 128, BATCH * NQ / 128), blk>>>(pO, Wout, bout, out,
                                                        BATCH * NQ, DQ, INNER);
}

// round 4
// speedup vs baseline: 1.1132x; 1.1079x over previous
#include <cuda_runtime.h>

#define BATCH 4
#define NQ    2048
#define NK    2048
#define DQ    1024
#define NH    8
#define HD    64
#define INNER 512
#define KKEEP 64

// Scratch (device globals; allocation-free contract)
__device__ float g_Q [BATCH * NQ * INNER];          // 16.8 MB
__device__ float g_KV[BATCH * NK * 2 * INNER];      // 33.5 MB  (K: cols 0..511, V: 512..1023)
__device__ float g_S [134217728];                   // 512 MB   sim [B*H][NQ][NK]
__device__ float g_O [BATCH * NQ * INNER];          // 16.8 MB

// ---------------------------------------------------------------------------
// fp32 SGEMM (NN), double-buffered: C[M,N] = A[M,K] @ B[K,N] (+ bias)
// 128x128 tile, BK=8, 256 threads, 8x8 microtile, 2-stage smem pipeline.
// ---------------------------------------------------------------------------
__global__ void __launch_bounds__(256) sgemm_nn(
    const float* __restrict__ A, const float* __restrict__ Bm,
    const float* __restrict__ bias, float* __restrict__ C,
    int M, int N, int K)
{
    __shared__ float As[2][8][128];
    __shared__ float Bs[2][8][128];
    const int tid  = threadIdx.x;
    const int row0 = blockIdx.y * 128, col0 = blockIdx.x * 128;
    const int tx   = tid & 15, ty = tid >> 4;
    const int a_row = tid >> 1, a_k = (tid & 1) * 4;
    const int b_k   = tid >> 5, b_col = (tid & 31) * 4;
    const float* Ap = A  + (size_t)(row0 + a_row) * K + a_k;
    const float* Bp = Bm + (size_t)b_k * N + col0 + b_col;

    float acc[8][8];
#pragma unroll
    for (int i = 0; i < 8; i++)
#pragma unroll
        for (int j = 0; j < 8; j++) acc[i][j] = 0.f;

    {
        float4 av = *(const float4*)Ap;
        float4 bv = *(const float4*)Bp;
        As[0][a_k + 0][a_row] = av.x;
        As[0][a_k + 1][a_row] = av.y;
        As[0][a_k + 2][a_row] = av.z;
        As[0][a_k + 3][a_row] = av.w;
        *(float4*)&Bs[0][b_k][b_col] = bv;
    }
    __syncthreads();

    int buf = 0;
    for (int k0 = 8; k0 <= K; k0 += 8) {
        const bool has = (k0 < K);
        float4 av, bv;
        if (has) {
            av = *(const float4*)(Ap + k0);
            bv = *(const float4*)(Bp + (size_t)k0 * N);
        }
#pragma unroll
        for (int kk = 0; kk < 8; kk++) {
            float af[8], bf[8];
            *(float4*)&af[0] = *(const float4*)&As[buf][kk][ty * 4];
            *(float4*)&af[4] = *(const float4*)&As[buf][kk][ty * 4 + 64];
            *(float4*)&bf[0] = *(const float4*)&Bs[buf][kk][tx * 4];
            *(float4*)&bf[4] = *(const float4*)&Bs[buf][kk][tx * 4 + 64];
#pragma unroll
            for (int i = 0; i < 8; i++)
#pragma unroll
                for (int j = 0; j < 8; j++)
                    acc[i][j] += af[i] * bf[j];
        }
        if (has) {
            const int nb = buf ^ 1;
            As[nb][a_k + 0][a_row] = av.x;
            As[nb][a_k + 1][a_row] = av.y;
            As[nb][a_k + 2][a_row] = av.z;
            As[nb][a_k + 3][a_row] = av.w;
            *(float4*)&Bs[nb][b_k][b_col] = bv;
            __syncthreads();
            buf = nb;
        }
    }

#pragma unroll
    for (int ih = 0; ih < 2; ih++)
#pragma unroll
        for (int ii = 0; ii < 4; ii++) {
            int row = row0 + ty * 4 + ih * 64 + ii;
            float* Cp = C + (size_t)row * N + col0;
#pragma unroll
            for (int jh = 0; jh < 2; jh++) {
                int c = tx * 4 + jh * 64;
                float4 v;
                v.x = acc[ih * 4 + ii][jh * 4 + 0];
                v.y = acc[ih * 4 + ii][jh * 4 + 1];
                v.z = acc[ih * 4 + ii][jh * 4 + 2];
                v.w = acc[ih * 4 + ii][jh * 4 + 3];
                if (bias) {
                    v.x += bias[col0 + c + 0];
                    v.y += bias[col0 + c + 1];
                    v.z += bias[col0 + c + 2];
                    v.w += bias[col0 + c + 3];
                }
                *(float4*)(Cp + c) = v;
            }
        }
}

// ---------------------------------------------------------------------------
// sim[bh][i][j] = scale * sum_d Q[b,i,h*64+d] * K[b,j,h*64+d]   (NT, K=64)
// 128x128 tile, whole K=64 in smem (64KB dynamic), 256 threads, 8x8 microtile.
// ---------------------------------------------------------------------------
__global__ void __launch_bounds__(256) sim_nt(
    const float* __restrict__ Q, const float* __restrict__ KV, float* __restrict__ S)
{
    extern __shared__ float smem[];
    float* Qs = smem;              // [64][128]  (d-major)
    float* Ks = smem + 64 * 128;   // [64][128]
    const int bh = blockIdx.z, b = bh >> 3, h = bh & 7;
    const int i0 = blockIdx.y * 128, j0 = blockIdx.x * 128;
    const int tid = threadIdx.x;

#pragma unroll
    for (int l = 0; l < 8; l++) {
        int idx = tid + l * 256;
        int row = idx >> 4, d0 = (idx & 15) * 4;
        float4 a = *(const float4*)(Q  + (size_t)(b * NQ + i0 + row) * INNER       + h * HD + d0);
        Qs[(d0 + 0) * 128 + row] = a.x; Qs[(d0 + 1) * 128 + row] = a.y;
        Qs[(d0 + 2) * 128 + row] = a.z; Qs[(d0 + 3) * 128 + row] = a.w;
        float4 v = *(const float4*)(KV + (size_t)(b * NK + j0 + row) * (2 * INNER) + h * HD + d0);
        Ks[(d0 + 0) * 128 + row] = v.x; Ks[(d0 + 1) * 128 + row] = v.y;
        Ks[(d0 + 2) * 128 + row] = v.z; Ks[(d0 + 3) * 128 + row] = v.w;
    }
    __syncthreads();

    const int tx = tid & 15, ty = tid >> 4;
    float acc[8][8];
#pragma unroll
    for (int i = 0; i < 8; i++)
#pragma unroll
        for (int j = 0; j < 8; j++) acc[i][j] = 0.f;

#pragma unroll 4
    for (int d = 0; d < 64; d++) {
        float af[8], bf[8];
        *(float4*)&af[0] = *(const float4*)(Qs + d * 128 + ty * 4);
        *(float4*)&af[4] = *(const float4*)(Qs + d * 128 + ty * 4 + 64);
        *(float4*)&bf[0] = *(const float4*)(Ks + d * 128 + tx * 4);
        *(float4*)&bf[4] = *(const float4*)(Ks + d * 128 + tx * 4 + 64);
#pragma unroll
        for (int i = 0; i < 8; i++)
#pragma unroll
            for (int j = 0; j < 8; j++)
                acc[i][j] += af[i] * bf[j];
    }

    const float scale = 0.125f;   // 64^-0.5
#pragma unroll
    for (int ih = 0; ih < 2; ih++)
#pragma unroll
        for (int ii = 0; ii < 4; ii++) {
            int row = i0 + ty * 4 + ih * 64 + ii;
            float* Sp = S + ((size_t)bh * NQ + row) * NK + j0;
#pragma unroll
            for (int jh = 0; jh < 2; jh++) {
                int c = tx * 4 + jh * 64;
                float4 v;
                v.x = acc[ih * 4 + ii][jh * 4 + 0] * scale;
                v.y = acc[ih * 4 + ii][jh * 4 + 1] * scale;
                v.z = acc[ih * 4 + ii][jh * 4 + 2] * scale;
                v.w = acc[ih * 4 + ii][jh * 4 + 3] * scale;
                *(float4*)(Sp + c) = v;
            }
        }
}

// ---------------------------------------------------------------------------
// Per query row: exact top-64 (2048-bin radix threshold, fully PARALLEL scans),
// ties broken by lowest index (= jax.lax.top_k), softmax over survivors,
// sparse PV. One block (128 threads) per row.
// ---------------------------------------------------------------------------
__device__ __forceinline__ unsigned fkey(float f) {
    unsigned u = __float_as_uint(f);
    return (u & 0x80000000u) ? ~u : (u | 0x80000000u);
}

__global__ void __launch_bounds__(128) topk_attn(
    const float* __restrict__ S, const float* __restrict__ KV, float* __restrict__ O)
{
    const int r  = blockIdx.x;
    const int bh = r >> 11, i = r & 2047;
    const int b  = bh >> 3, h = bh & 7;
    const float* srow = S + (size_t)r * NK;

    __shared__ unsigned hist[2048];
    __shared__ unsigned seg[128];      // suffix-scan workspace
    __shared__ float cval[2048];
    __shared__ unsigned short cidx[2048];
    __shared__ float selv[80];
    __shared__ int   seli[80];
    __shared__ int   s_nsel, s_ncand, s_thrbin, s_m, s_sseg, s_base;
    __shared__ float s_max, s_wsum;
    __shared__ float w[64];
    __shared__ float part[64];

    const int tid = threadIdx.x;
    for (int t = tid; t < 2048; t += 128) hist[t] = 0u;
    if (tid == 0) { s_nsel = 0; s_ncand = 0; }
    __syncthreads();

    float vals[16];
#pragma unroll
    for (int t = 0; t < 4; t++) {
        float4 v = ((const float4*)srow)[tid + t * 128];
        vals[t * 4 + 0] = v.x; vals[t * 4 + 1] = v.y;
        vals[t * 4 + 2] = v.z; vals[t * 4 + 3] = v.w;
    }
#pragma unroll
    for (int t = 0; t < 16; t++)
        atomicAdd(&hist[fkey(vals[t]) >> 21], 1u);
    __syncthreads();

    // per-thread: sum of its 16-bin segment
    {
        unsigned s = 0;
#pragma unroll
        for (int q = 0; q < 16; q++) s += hist[tid * 16 + q];
        seg[tid] = s;
    }
    __syncthreads();

    // parallel suffix scan over 128 segments (Hillis-Steele, 7 steps)
#pragma unroll
    for (int off = 1; off < 128; off <<= 1) {
        unsigned v = seg[tid] + ((tid + off < 128) ? seg[tid + off] : 0u);
        __syncthreads();
        seg[tid] = v;
        __syncthreads();
    }
    // seg[t] = count of keys in segments >= t. Find crossing segment.
    {
        unsigned sfx  = seg[tid];
        unsigned sfx1 = (tid < 127) ? seg[tid + 1] : 0u;
        if (sfx >= KKEEP && sfx1 < KKEEP) { s_sseg = tid; s_base = (int)sfx1; }
    }
    __syncthreads();
    const int sseg = s_sseg, base = s_base;

    // within-segment crossing via warp 0 (16 lanes, shuffle suffix scan)
    if (tid < 32) {
        const int lane = tid;
        unsigned hv = (lane < 16) ? hist[sseg * 16 + lane] : 0u;
        unsigned sfx = hv;
#pragma unroll
        for (int off = 1; off < 16; off <<= 1) {
            unsigned t2 = __shfl_down_sync(0xffffffffu, sfx, off);
            if (lane + off < 16) sfx += t2;
        }
        if (lane < 16) {
            int above = base + (int)(sfx - hv);   // count strictly above this bin
            if (base + (int)sfx >= KKEEP && above < KKEEP) {
                s_thrbin = sseg * 16 + lane;
                s_m = KKEEP - above;
            }
        }
    }
    __syncthreads();
    const int thrbin = s_thrbin, m = s_m;

    // selection pass
#pragma unroll
    for (int t = 0; t < 16; t++) {
        int bin = (int)(fkey(vals[t]) >> 21);
        int j = (tid + (t >> 2) * 128) * 4 + (t & 3);
        if (bin > thrbin) {
            int p = atomicAdd(&s_nsel, 1);
            selv[p] = vals[t]; seli[p] = j;
        } else if (bin == thrbin) {
            int p = atomicAdd(&s_ncand, 1);
            cval[p] = vals[t]; cidx[p] = (unsigned short)j;
        }
    }
    __syncthreads();

    // tie-rank within threshold bin (ncand is small: ~10-30 typical)
    const int ncand = s_ncand;
    for (int cpos = tid; cpos < ncand; cpos += 128) {
        float v = cval[cpos]; int jj = cidx[cpos];
        int rank = 0;
        for (int o = 0; o < ncand; o++) {
            float v2 = cval[o];
            rank += (v2 > v) || (v2 == v && (int)cidx[o] < jj);
        }
        if (rank < m) {
            int p = atomicAdd(&s_nsel, 1);
            selv[p] = v; seli[p] = jj;
        }
    }
    __syncthreads();   // s_nsel == 64 exactly

    if (tid < 32) {
        float mx = fmaxf(selv[tid], selv[tid + 32]);
#pragma unroll
        for (int off = 16; off; off >>= 1)
            mx = fmaxf(mx, __shfl_xor_sync(0xffffffffu, mx, off));
        if (tid == 0) s_max = mx;
    }
    __syncthreads();
    if (tid < 64) w[tid] = expf(selv[tid] - s_max);
    __syncthreads();
    if (tid < 32) {
        float s = w[tid] + w[tid + 32];
#pragma unroll
        for (int off = 16; off; off >>= 1)
            s += __shfl_xor_sync(0xffffffffu, s, off);
        if (tid == 0) s_wsum = s;
    }
    __syncthreads();

    const int g = tid >> 6, d = tid & 63;
    const float* Vbase = KV + (size_t)b * NK * (2 * INNER) + INNER + h * HD + d;
    float acc = 0.f;
#pragma unroll 4
    for (int jj = 0; jj < 32; jj++) {
        int j = g * 32 + jj;
        acc += w[j] * Vbase[(size_t)seli[j] * (2 * INNER)];
    }
    if (g == 1) part[d] = acc;
    __syncthreads();
    if (g == 0) {
        float o = (acc + part[d]) / s_wsum;
        O[((size_t)(b * NQ + i)) * INNER + h * HD + d] = o;
    }
}

// ---------------------------------------------------------------------------
extern "C" void kernel_launch(void* const* d_in, const int* in_sizes, int n_in,
                              void* d_out, int out_size)
{
    const float* x    = (const float*)d_in[0];
    const float* ctx  = (const float*)d_in[1];
    const float* Wq   = (const float*)d_in[2];
    const float* Wkv  = (const float*)d_in[3];
    const float* Wout = (const float*)d_in[4];
    const float* bout = (const float*)d_in[5];
    float* out = (float*)d_out;

    float *pQ, *pKV, *pS, *pO;
    cudaGetSymbolAddress((void**)&pQ,  g_Q);
    cudaGetSymbolAddress((void**)&pKV, g_KV);
    cudaGetSymbolAddress((void**)&pS,  g_S);
    cudaGetSymbolAddress((void**)&pO,  g_O);

    const int simSmem = 2 * 64 * 128 * sizeof(float);   // 64 KB
    cudaFuncSetAttribute(sim_nt, cudaFuncAttributeMaxDynamicSharedMemorySize, simSmem);

    dim3 blk(256);
    // Q = x @ Wq            [8192,1024] @ [1024,512]
    sgemm_nn<<<dim3(INNER / 128, BATCH * NQ / 128), blk>>>(x, Wq, nullptr, pQ,
                                                           BATCH * NQ, INNER, DQ);
    // KV = ctx @ Wkv        [8192,1024] @ [1024,1024]
    sgemm_nn<<<dim3(2 * INNER / 128, BATCH * NK / 128), blk>>>(ctx, Wkv, nullptr, pKV,
                                                               BATCH * NK, 2 * INNER, DQ);
    // sim = Q @ K^T * scale (batched per head)
    sim_nt<<<dim3(NK / 128, NQ / 128, BATCH * NH), blk, simSmem>>>(pQ, pKV, pS);
    // exact top-64 + softmax + sparse PV
    topk_attn<<<dim3(BATCH * NH * NQ), dim3(128)>>>(pS, pKV, pO);
    // out = O @ Wout + bout [8192,512] @ [512,1024]
    sgemm_nn<<<dim3(DQ / 128, BATCH * NQ / 128), blk>>>(pO, Wout, bout, out,
                                                        BATCH * NQ, DQ, INNER);
}